// round 16
// baseline (speedup 1.0000x reference)
#include <cuda_runtime.h>
#include <cstdint>

// Per-row top-k (k=64) of x[16384, 8192] fp32, scattered back densely.
// R16: split streams. Kernel 1 zero-fills out (pure 512MB write stream,
// streaming stores). Kernel 2 is the proven R8 select pipeline (interleaved
// unconditional 64-bucket histogram under the load latency, bucket suffix
// scan, register compaction, tiny exact rank select, exact tie handling)
// but writes ONLY the ~64 winners per row (sparse scatter) instead of the
// dense 512MB write. Each kernel runs a single-direction DRAM stream.

#define TPB   256
#define COLS  8192
#define VPT   8            // float4 per thread
#define EPT   32           // elements per thread
#define NB    64           // buckets

// Monotone bucketing: clamp(floor(f*8), -32, 31) + 32. NaN -> bucket 0 via
// fmaxf/fminf NaN absorption (inputs are Gaussian; NaN-free in practice).
__device__ __forceinline__ int bucketOf(float f) {
    return __float2int_rd(fminf(fmaxf(f * 8.0f, -32.0f), 31.0f)) + 32;
}

// ---------------- Kernel 1: pure write stream (zero fill) ----------------
__global__ void __launch_bounds__(256)
zero_kernel(float4* __restrict__ out4, int n4)
{
    int i      = blockIdx.x * blockDim.x + threadIdx.x;
    int stride = gridDim.x * blockDim.x;
    const float4 z = make_float4(0.0f, 0.0f, 0.0f, 0.0f);
    for (; i < n4; i += stride)
        __stcs(&out4[i], z);
}

// ---------- Kernel 2: read stream + select + sparse winner scatter ----------
__global__ void __launch_bounds__(TPB, 4)
topk_scatter_kernel(const float* __restrict__ x,
                    const unsigned int* __restrict__ kp,
                    float* __restrict__ out)
{
    const int row  = blockIdx.x;
    const int t    = threadIdx.x;
    const int lane = t & 31;
    const int w    = t >> 5;

    __shared__ float    buf[COLS];      // candidates (worst case: whole row)
    __shared__ uint32_t hist[NB];
    __shared__ uint32_t wsum[2];
    __shared__ uint32_t sh_sel, sh_hi, sh_cnt, sh_keep, sh_neq, sh_tc;
    __shared__ float    sh_thr;

    const float4* __restrict__ xr     = reinterpret_cast<const float4*>(x + (size_t)row * COLS);
    float* __restrict__        orow_f = out + (size_t)row * COLS;

    if (t < NB) hist[t] = 0u;
    if (t == 0) sh_cnt = 0u;
    __syncthreads();

    // ---- load row (read-once -> streaming) and count buckets (interleaved,
    // unconditional: this work hides under the LDG latency — proven in R8) ----
    float val[EPT];
#pragma unroll
    for (int j = 0; j < VPT; j++) {
        float4 v = __ldcs(&xr[t + j * TPB]);
        val[4*j+0] = v.x; atomicAdd(&hist[bucketOf(v.x)], 1u);
        val[4*j+1] = v.y; atomicAdd(&hist[bucketOf(v.y)], 1u);
        val[4*j+2] = v.z; atomicAdd(&hist[bucketOf(v.z)], 1u);
        val[4*j+3] = v.w; atomicAdd(&hist[bucketOf(v.w)], 1u);
    }

    // k input (defensive parse; expected 64)
    uint32_t K = 64u;
    if (kp) {
        uint32_t raw = __ldg(kp);
        if (raw >= 1u && raw <= (uint32_t)COLS) {
            K = raw;
        } else {
            float f = __uint_as_float(raw);
            if (f >= 1.0f && f <= (float)COLS) K = (uint32_t)f;
        }
    }
    __syncthreads();

    // ---- select bucket containing the K-th largest (2 warps active) ----
    uint32_t tot = 0, s = 0;
    if (t < NB) {
        tot = hist[t];
        s = tot;
#pragma unroll
        for (int off = 1; off < 32; off <<= 1) {
            uint32_t v = __shfl_down_sync(0xFFFFFFFFu, s, off);
            if (lane + off < 32) s += v;
        }
        if (lane == 0) wsum[w] = s;
    }
    __syncthreads();
    if (t < NB) {
        uint32_t S = s + ((w == 0) ? wsum[1] : 0u);   // suffix over bins >= t
        if (S >= K && (S - tot) < K) {
            sh_sel = (uint32_t)t;
            sh_hi  = S - tot;
        }
    }
    __syncthreads();

    const uint32_t sel = sh_sel;
    const uint32_t kkw = K - sh_hi;                   // rank within bucket (>=1)

    // value-space interval of the selected bucket (exact: n*0.125 is exact fp32)
    const float Flo  = (float)((int)sel - 32) * 0.125f;
    const float Fhi  = (float)((int)sel - 31) * 0.125f;
    const bool  noLo = (sel == 0);
    const bool  noHi = (sel == 63);

    // ---- compact survivors (few matches -> predicated atomic is cheapest) ----
#pragma unroll
    for (int e = 0; e < EPT; e++) {
        float f = val[e];
        if ((noLo || f >= Flo) && (noHi || f < Fhi))
            buf[atomicAdd(&sh_cnt, 1u)] = f;
    }
    __syncthreads();

    const uint32_t cnt = sh_cnt;

    // ---- exact rank select among candidates (broadcast LDS inner loop) ----
    for (uint32_t i = t; i < cnt; i += TPB) {
        float fi = buf[i];
        uint32_t g = 0, eq = 0;
        for (uint32_t j = 0; j < cnt; j++) {
            float fj = buf[j];
            g  += (fj > fi);
            eq += (fj == fi);
        }
        if (g < kkw && g + eq >= kkw) {
            sh_thr  = fi;          // exact K-th largest value
            sh_keep = kkw - g;     // threshold-equals to keep
            sh_neq  = eq;          // total threshold-equals
        }
    }
    __syncthreads();

    const float    thresh = sh_thr;
    const uint32_t keep   = sh_keep;
    const uint32_t neq    = sh_neq;

    // ---- tie resolution (exact lowest-index-first; rare path) ----
    int t_idx = COLS - 1;
    if (neq > keep) {
        int lo = 0, hi = COLS - 1;
        while (lo < hi) {
            int mid = (lo + hi) >> 1;
            if (t == 0) sh_tc = 0u;
            __syncthreads();
            uint32_t local = 0;
#pragma unroll
            for (int j = 0; j < VPT; j++) {
                int base = 4 * (t + j * TPB);
#pragma unroll
                for (int c = 0; c < 4; c++) {
                    if (val[4*j + c] == thresh && (base + c) <= mid) local++;
                }
            }
            if (local) atomicAdd(&sh_tc, local);
            __syncthreads();
            if (sh_tc >= keep) hi = mid; else lo = mid + 1;
            __syncthreads();
        }
        t_idx = lo;
    }

    // ---- sparse scatter: write ONLY the K winners (~64 stores per row) ----
    // Same predicates as R8's dense write phase; zeros already in place from
    // kernel 1 (ordered before this kernel in-stream).
    if (neq == keep) {
#pragma unroll
        for (int j = 0; j < VPT; j++) {
            const int base = 4 * (t + j * TPB);
#pragma unroll
            for (int c = 0; c < 4; c++) {
                float f = val[4*j + c];
                if (f >= thresh) __stcs(&orow_f[base + c], f);
            }
        }
    } else {
#pragma unroll
        for (int j = 0; j < VPT; j++) {
            const int base = 4 * (t + j * TPB);
#pragma unroll
            for (int c = 0; c < 4; c++) {
                float f = val[4*j + c];
                if (f > thresh || (f == thresh && (base + c) <= t_idx))
                    __stcs(&orow_f[base + c], f);
            }
        }
    }
}

extern "C" void kernel_launch(void* const* d_in, const int* in_sizes, int n_in,
                              void* d_out, int out_size)
{
    const float* x = (const float*)d_in[0];
    const unsigned int* kp = (n_in >= 2) ? (const unsigned int*)d_in[1] : nullptr;

    const int rows = out_size / COLS;   // 16384
    const int n4   = out_size / 4;      // float4 count

    zero_kernel<<<8192, 256>>>((float4*)d_out, n4);
    topk_scatter_kernel<<<rows, TPB>>>(x, kp, (float*)d_out);
}